// round 11
// baseline (speedup 1.0000x reference)
#include <cuda_runtime.h>
#include <cuda_bf16.h>
#include <cstdint>

// Problem constants
#define BB 8
#define NN 2048
#define DD 256
#define LL 2
#define MROWS (BB * NN)   // 16384

#define KC 64             // K per pipeline chunk
#define NSTAGES 3

// smem geometry (padded, no swizzle) — shared by both MMA kernels
#define PADK 72                      // 64 + 8 bf16 pad
#define ROWB (PADK * 2)              // 144 bytes per row
#define ASTAGE (128 * ROWB)          // 18432 B
#define STAGE_BYTES (2 * ASTAGE)     // 36864 B (A + B)
#define MMA_SMEM (NSTAGES * STAGE_BYTES)  // 110592 B

// ---------------------------------------------------------------------------
// Scratch (static __device__ arrays — no allocation allowed)
// ---------------------------------------------------------------------------
__device__ __nv_bfloat16 g_adj_bf[(size_t)BB * NN * NN];    // adj bf16
__device__ __nv_bfloat16 g_nodes_bf[(size_t)MROWS * DD];    // nodes bf16 (plain)
__device__ __nv_bfloat16 g_xbf[(size_t)MROWS * DD];         // activations bf16 (plain)
__device__ __nv_bfloat16 g_xT[(size_t)BB * DD * NN];        // x transposed [b][d][n]
__device__ __nv_bfloat16 g_S[(size_t)MROWS * DD];           // S = adj @ x (bf16)
__device__ __nv_bfloat16 g_W0bf[(size_t)LL * DD * DD];      // W0_w bf16
__device__ __nv_bfloat16 g_Wrbf[(size_t)LL * DD * DD];      // Wr_w bf16
__device__ float g_denom[MROWS];                            // row-sum(adj) + 1

// ---------------------------------------------------------------------------
// PTX helpers (plain-sm_103-safe)
// ---------------------------------------------------------------------------
__device__ __forceinline__ uint32_t smem_u32(const void* p) {
    uint32_t a;
    asm("{ .reg .u64 t; cvta.to.shared.u64 t, %1; cvt.u32.u64 %0, t; }" : "=r"(a) : "l"(p));
    return a;
}
__device__ __forceinline__ void cp_async16(uint32_t saddr, const void* g) {
    asm volatile("cp.async.cg.shared.global [%0], [%1], 16;" :: "r"(saddr), "l"(g) : "memory");
}
__device__ __forceinline__ void cp_commit() {
    asm volatile("cp.async.commit_group;" ::: "memory");
}
template <int N>
__device__ __forceinline__ void cp_wait() {
    asm volatile("cp.async.wait_group %0;" :: "n"(N) : "memory");
}
__device__ __forceinline__ void ldsm_x4(uint32_t (&r)[4], uint32_t addr) {
    asm volatile("ldmatrix.sync.aligned.m8n8.x4.shared.b16 {%0,%1,%2,%3}, [%4];"
                 : "=r"(r[0]), "=r"(r[1]), "=r"(r[2]), "=r"(r[3]) : "r"(addr));
}
__device__ __forceinline__ void mma_bf16(float (&c)[4], const uint32_t (&a)[4],
                                         uint32_t b0, uint32_t b1) {
    asm volatile(
        "mma.sync.aligned.m16n8k16.row.col.f32.bf16.bf16.f32 "
        "{%0,%1,%2,%3}, {%4,%5,%6,%7}, {%8,%9}, {%0,%1,%2,%3};"
        : "+f"(c[0]), "+f"(c[1]), "+f"(c[2]), "+f"(c[3])
        : "r"(a[0]), "r"(a[1]), "r"(a[2]), "r"(a[3]), "r"(b0), "r"(b1));
}
__device__ __forceinline__ uint32_t pack_bf16x2(float x, float y) {
    __nv_bfloat162 v = __floats2bfloat162_rn(x, y);
    return *(uint32_t*)&v;
}
__device__ __forceinline__ void cvt8(__nv_bfloat16* t, float4 v0, float4 v1) {
    t[0] = __float2bfloat16(v0.x); t[1] = __float2bfloat16(v0.y);
    t[2] = __float2bfloat16(v0.z); t[3] = __float2bfloat16(v0.w);
    t[4] = __float2bfloat16(v1.x); t[5] = __float2bfloat16(v1.y);
    t[6] = __float2bfloat16(v1.z); t[7] = __float2bfloat16(v1.w);
}

// ---------------------------------------------------------------------------
// Merged prologue:
//   blocks [0, MROWS)        : adj row -> bf16 + denom rowsum
//   blocks [MROWS, +256)     : nodes fp32 -> bf16 plain + transposed (g_xT)
//   blocks [.., +2*NB_W)     : weights -> bf16
// ---------------------------------------------------------------------------
#define NB_W ((LL * DD * DD) / (256 * 8))   // 64

__global__ void prologue_kernel(const float* __restrict__ adj,
                                const float* __restrict__ nodes,
                                const float* __restrict__ W0w,
                                const float* __restrict__ Wrw) {
    int bid = blockIdx.x;
    int tid = threadIdx.x;

    if (bid < MROWS) {
        int row = bid;
        const float4* src = (const float4*)(adj + (size_t)row * NN);
        __nv_bfloat16* dst = g_adj_bf + (size_t)row * NN;
        float4 v0 = src[tid * 2 + 0];
        float4 v1 = src[tid * 2 + 1];
        float s = v0.x + v0.y + v0.z + v0.w + v1.x + v1.y + v1.z + v1.w;
        __nv_bfloat16 tmp[8];
        cvt8(tmp, v0, v1);
        *(uint4*)(dst + tid * 8) = *(const uint4*)tmp;

        __shared__ float red[8];
#pragma unroll
        for (int o = 16; o; o >>= 1) s += __shfl_xor_sync(0xffffffffu, s, o);
        if ((tid & 31) == 0) red[tid >> 5] = s;
        __syncthreads();
        if (tid < 8) {
            float t = red[tid];
#pragma unroll
            for (int o = 4; o; o >>= 1) t += __shfl_xor_sync(0xffu, t, o);
            if (tid == 0) g_denom[row] = t + 1.0f;
        }
        return;
    }

    int t = bid - MROWS;
    if (t < 256) {
        // nodes 128x128 tile: fp32 -> bf16, plain write + smem transpose write
        __shared__ __nv_bfloat16 sm[128 * 144];
        int dt = t & 1, nt = (t >> 1) & 15, bb = t >> 5;
#pragma unroll
        for (int it = 0; it < 8; ++it) {
            int idx = it * 256 + tid;
            int rr = idx >> 4, ch = idx & 15;
            size_t off = ((size_t)bb * NN + nt * 128 + rr) * DD + dt * 128 + ch * 8;
            float4 v0 = *(const float4*)(nodes + off);
            float4 v1 = *(const float4*)(nodes + off + 4);
            __nv_bfloat16 tmp[8];
            cvt8(tmp, v0, v1);
            uint4 pk = *(const uint4*)tmp;
            *(uint4*)&sm[rr * 144 + ch * 8] = pk;
            *(uint4*)(g_nodes_bf + off) = pk;
        }
        __syncthreads();
#pragma unroll
        for (int it = 0; it < 8; ++it) {
            int idx = it * 256 + tid;
            int d = idx >> 4, ch = idx & 15;
            __nv_bfloat16 tmp[8];
#pragma unroll
            for (int j = 0; j < 8; ++j) tmp[j] = sm[(ch * 8 + j) * 144 + d];
            *(uint4*)(g_xT + (size_t)bb * DD * NN + (size_t)(dt * 128 + d) * NN
                      + nt * 128 + ch * 8) = *(const uint4*)tmp;
        }
        return;
    }

    int b2 = t - 256;
    const float* src;
    __nv_bfloat16* dst;
    size_t off;
    if (b2 < NB_W) { src = W0w; dst = g_W0bf; off = (size_t)b2 * 256 * 8; }
    else           { src = Wrw; dst = g_Wrbf; off = (size_t)(b2 - NB_W) * 256 * 8; }
    size_t p = off + (size_t)tid * 8;
    float4 v0 = *(const float4*)(src + p);
    float4 v1 = *(const float4*)(src + p + 4);
    __nv_bfloat16 tmp[8];
    cvt8(tmp, v0, v1);
    *(uint4*)(dst + p) = *(const uint4*)tmp;
}

// ---------------------------------------------------------------------------
// Big GEMM: S = adj @ x   (B = g_xT, K-major)
//   grid (2, 16, 8) = 256 CTAs, block 256, 2 CTA/SM (all resident)
// ---------------------------------------------------------------------------
#define NCHUNK (NN / KC)  // 32

__global__ void __launch_bounds__(256, 2)
nn_mma_kernel() {
    extern __shared__ char smem[];
    uint32_t sb = smem_u32(smem);

    int tid = threadIdx.x;
    int lane = tid & 31, wid = tid >> 5;
    int warp_m = wid & 3, warp_n = wid >> 2;
    int b = blockIdx.z;
    int row0 = blockIdx.y * 128;
    int col0 = blockIdx.x * 128;

    const __nv_bfloat16* Ag = g_adj_bf + (size_t)b * NN * NN + (size_t)row0 * NN;
    const __nv_bfloat16* Bg = g_xT + (size_t)b * DD * NN + (size_t)col0 * NN;

    float acc[2][8][4];
#pragma unroll
    for (int i = 0; i < 2; ++i)
#pragma unroll
        for (int j = 0; j < 8; ++j)
#pragma unroll
            for (int q = 0; q < 4; ++q) acc[i][j][q] = 0.f;

    uint32_t a_base = sb + (uint32_t)((warp_m * 32 + (lane & 15)) * ROWB + (lane >> 4) * 16);
    uint32_t b_base = sb + ASTAGE +
                      (uint32_t)((warp_n * 64 + (lane & 15)) * ROWB + (lane >> 4) * 16);

    auto load_stage = [&](int c, int s) {
        uint32_t as = sb + s * STAGE_BYTES;
        uint32_t bs = as + ASTAGE;
        int k0 = c * KC;
#pragma unroll
        for (int i = 0; i < 4; ++i) {
            int idx = i * 256 + tid;
            int r = idx >> 3, ch = idx & 7;
            cp_async16(as + r * ROWB + ch * 16, Ag + (size_t)r * NN + k0 + ch * 8);
        }
#pragma unroll
        for (int i = 0; i < 4; ++i) {
            int idx = i * 256 + tid;
            int r = idx >> 3, ch = idx & 7;
            cp_async16(bs + r * ROWB + ch * 16, Bg + (size_t)r * NN + k0 + ch * 8);
        }
        cp_commit();
    };

    auto compute_stage = [&](int s) {
        uint32_t as = a_base + s * STAGE_BYTES;
        uint32_t bs = b_base + s * STAGE_BYTES;
#pragma unroll
        for (int ks = 0; ks < 4; ++ks) {
            uint32_t af[2][4];
            ldsm_x4(af[0], as + 0 * 16 * ROWB + ks * 32);
            ldsm_x4(af[1], as + 1 * 16 * ROWB + ks * 32);
            uint32_t bf[4][4];
#pragma unroll
            for (int n2 = 0; n2 < 4; ++n2)
                ldsm_x4(bf[n2], bs + n2 * 16 * ROWB + ks * 32);
#pragma unroll
            for (int mf = 0; mf < 2; ++mf)
#pragma unroll
                for (int nf = 0; nf < 8; ++nf)
                    mma_bf16(acc[mf][nf], af[mf], bf[nf >> 1][nf & 1],
                             bf[nf >> 1][(nf & 1) + 2]);
        }
    };

    load_stage(0, 0);
    load_stage(1, 1);

    for (int c = 0; c < NCHUNK; ++c) {
        if (c + 1 < NCHUNK) cp_wait<1>(); else cp_wait<0>();
        __syncthreads();
        if (c + 2 < NCHUNK) load_stage(c + 2, (c + 2) % NSTAGES);
        compute_stage(c % NSTAGES);
    }

    int g = lane >> 2, tg = lane & 3;
#pragma unroll
    for (int mf = 0; mf < 2; ++mf) {
#pragma unroll
        for (int half = 0; half < 2; ++half) {
            int row = row0 + warp_m * 32 + mf * 16 + half * 8 + g;
            size_t grow = (size_t)b * NN + row;
#pragma unroll
            for (int nf = 0; nf < 8; ++nf) {
                int col = col0 + warp_n * 64 + nf * 8 + tg * 2;
                *(uint32_t*)(g_S + grow * DD + col) =
                    pack_bf16x2(acc[mf][nf][half * 2 + 0], acc[mf][nf][half * 2 + 1]);
            }
        }
    }
}

// ---------------------------------------------------------------------------
// epi kernel: acc = S@Wr^T + x@W0^T  (8 chunks, 3-stage)
//   out = relu((acc + b0 + (denom-1)*br) / denom)
//   final: dout = nodes + out; else: g_xbf (plain) + g_xT (transposed)
//   grid (2, 128), block 256, 2 CTA/SM
// ---------------------------------------------------------------------------
__global__ void __launch_bounds__(256, 2)
epi_mma_kernel(int use_x,
               const float* __restrict__ b0,
               const float* __restrict__ br,
               const float* __restrict__ nodes,
               float* __restrict__ dout,
               int layer, int final_layer) {
    extern __shared__ char smem[];
    uint32_t sb = smem_u32(smem);
    __nv_bfloat16* Ts = (__nv_bfloat16*)smem;    // aliases stage mem (epilogue only)

    int tid = threadIdx.x;
    int lane = tid & 31, wid = tid >> 5;
    int warp_m = wid & 3, warp_n = wid >> 2;
    int row0 = blockIdx.y * 128;
    int col0w = blockIdx.x * 128;

    const __nv_bfloat16* A0 = g_S + (size_t)row0 * DD;
    const __nv_bfloat16* A1 = (use_x ? g_xbf : g_nodes_bf) + (size_t)row0 * DD;
    const __nv_bfloat16* B0 = g_Wrbf + (size_t)layer * DD * DD + (size_t)col0w * DD;
    const __nv_bfloat16* B1 = g_W0bf + (size_t)layer * DD * DD + (size_t)col0w * DD;

    float acc[2][8][4];
#pragma unroll
    for (int i = 0; i < 2; ++i)
#pragma unroll
        for (int j = 0; j < 8; ++j)
#pragma unroll
            for (int q = 0; q < 4; ++q) acc[i][j][q] = 0.f;

    uint32_t a_base = sb + (uint32_t)((warp_m * 32 + (lane & 15)) * ROWB + (lane >> 4) * 16);
    uint32_t b_base = sb + ASTAGE +
                      (uint32_t)((warp_n * 64 + (lane & 15)) * ROWB + (lane >> 4) * 16);

    auto load_stage = [&](int c, int s) {
        uint32_t as = sb + s * STAGE_BYTES;
        uint32_t bs = as + ASTAGE;
        const __nv_bfloat16* Ag = (c < 4) ? A0 : A1;
        const __nv_bfloat16* Bg = (c < 4) ? B0 : B1;
        int k0 = (c & 3) * KC;
#pragma unroll
        for (int i = 0; i < 4; ++i) {
            int idx = i * 256 + tid;
            int r = idx >> 3, ch = idx & 7;
            cp_async16(as + r * ROWB + ch * 16, Ag + (size_t)r * DD + k0 + ch * 8);
        }
#pragma unroll
        for (int i = 0; i < 4; ++i) {
            int idx = i * 256 + tid;
            int r = idx >> 3, ch = idx & 7;
            cp_async16(bs + r * ROWB + ch * 16, Bg + (size_t)r * DD + k0 + ch * 8);
        }
        cp_commit();
    };

    auto compute_stage = [&](int s) {
        uint32_t as = a_base + s * STAGE_BYTES;
        uint32_t bs = b_base + s * STAGE_BYTES;
#pragma unroll
        for (int ks = 0; ks < 4; ++ks) {
            uint32_t af[2][4];
            ldsm_x4(af[0], as + 0 * 16 * ROWB + ks * 32);
            ldsm_x4(af[1], as + 1 * 16 * ROWB + ks * 32);
            uint32_t bf[4][4];
#pragma unroll
            for (int n2 = 0; n2 < 4; ++n2)
                ldsm_x4(bf[n2], bs + n2 * 16 * ROWB + ks * 32);
#pragma unroll
            for (int mf = 0; mf < 2; ++mf)
#pragma unroll
                for (int nf = 0; nf < 8; ++nf)
                    mma_bf16(acc[mf][nf], af[mf], bf[nf >> 1][nf & 1],
                             bf[nf >> 1][(nf & 1) + 2]);
        }
    };

    load_stage(0, 0);
    load_stage(1, 1);
    for (int c = 0; c < 8; ++c) {
        if (c + 1 < 8) cp_wait<1>(); else cp_wait<0>();
        __syncthreads();
        if (c + 2 < 8) load_stage(c + 2, (c + 2) % NSTAGES);
        compute_stage(c % NSTAGES);
    }

    int g = lane >> 2, tg = lane & 3;

    if (final_layer) {
#pragma unroll
        for (int mf = 0; mf < 2; ++mf)
#pragma unroll
            for (int half = 0; half < 2; ++half) {
                int rl = warp_m * 32 + mf * 16 + half * 8 + g;
                size_t grow = (size_t)row0 + rl;
                float den = g_denom[grow];
                float inv = 1.0f / den;
                float rs = den - 1.0f;
#pragma unroll
                for (int nf = 0; nf < 8; ++nf) {
                    int m = col0w + warp_n * 64 + nf * 8 + tg * 2;
                    float2 bi0 = *(const float2*)(b0 + m);
                    float2 bir = *(const float2*)(br + m);
                    float vx = fmaxf((acc[mf][nf][half * 2 + 0] + bi0.x + rs * bir.x) * inv, 0.f);
                    float vy = fmaxf((acc[mf][nf][half * 2 + 1] + bi0.y + rs * bir.y) * inv, 0.f);
                    float2 nd = *(const float2*)(nodes + grow * DD + m);
                    *(float2*)(dout + grow * DD + m) = make_float2(vx + nd.x, vy + nd.y);
                }
            }
    } else {
        __syncthreads();     // stage smem fully consumed; safe to alias as Ts
#pragma unroll
        for (int mf = 0; mf < 2; ++mf)
#pragma unroll
            for (int half = 0; half < 2; ++half) {
                int rl = warp_m * 32 + mf * 16 + half * 8 + g;
                size_t grow = (size_t)row0 + rl;
                float den = g_denom[grow];
                float inv = 1.0f / den;
                float rs = den - 1.0f;
#pragma unroll
                for (int nf = 0; nf < 8; ++nf) {
                    int cl = warp_n * 64 + nf * 8 + tg * 2;
                    int m = col0w + cl;
                    float2 bi0 = *(const float2*)(b0 + m);
                    float2 bir = *(const float2*)(br + m);
                    float vx = fmaxf((acc[mf][nf][half * 2 + 0] + bi0.x + rs * bir.x) * inv, 0.f);
                    float vy = fmaxf((acc[mf][nf][half * 2 + 1] + bi0.y + rs * bir.y) * inv, 0.f);
                    *(uint32_t*)(g_xbf + grow * DD + m) = pack_bf16x2(vx, vy);
                    Ts[(size_t)cl * 136 + rl] = __float2bfloat16(vx);
                    Ts[(size_t)(cl + 1) * 136 + rl] = __float2bfloat16(vy);
                }
            }
        __syncthreads();
        int b = row0 >> 11;
        int nloc = row0 & 2047;
        int dl = tid >> 1, seg = tid & 1;
        __nv_bfloat16* dst = g_xT + (size_t)b * DD * NN + (size_t)(col0w + dl) * NN
                             + nloc + seg * 64;
        const __nv_bfloat16* srcp = Ts + (size_t)dl * 136 + seg * 64;
#pragma unroll
        for (int q = 0; q < 8; ++q)
            *(uint4*)(dst + q * 8) = *(const uint4*)(srcp + q * 8);
    }
}

// ---------------------------------------------------------------------------
// Launch
// ---------------------------------------------------------------------------
extern "C" void kernel_launch(void* const* d_in, const int* in_sizes, int n_in,
                              void* d_out, int out_size) {
    const float* nodes = (const float*)d_in[0];
    const float* adj   = (const float*)d_in[1];
    const float* W0w   = (const float*)d_in[2];
    const float* W0b   = (const float*)d_in[3];
    const float* Wrw   = (const float*)d_in[4];
    const float* Wrb   = (const float*)d_in[5];
    float* out = (float*)d_out;

    cudaFuncSetAttribute(nn_mma_kernel, cudaFuncAttributeMaxDynamicSharedMemorySize,
                         MMA_SMEM);
    cudaFuncSetAttribute(epi_mma_kernel, cudaFuncAttributeMaxDynamicSharedMemorySize,
                         MMA_SMEM);

    prologue_kernel<<<MROWS + 256 + 2 * NB_W, 256>>>(adj, nodes, W0w, Wrw);

    dim3 grid_nn(DD / 128, NN / 128, BB);  // (2, 16, 8)
    dim3 grid_epi(2, MROWS / 128);         // (2, 128)

    for (int l = 0; l < LL; ++l) {
        nn_mma_kernel<<<grid_nn, 256, MMA_SMEM>>>();   // S = adj @ x_l
        epi_mma_kernel<<<grid_epi, 256, MMA_SMEM>>>(
            (l == 0) ? 0 : 1,
            W0b + (size_t)l * DD, Wrb + (size_t)l * DD,
            nodes, out, l, (l == LL - 1) ? 1 : 0);
    }
}

// round 14
// speedup vs baseline: 1.5950x; 1.5950x over previous
#include <cuda_runtime.h>
#include <cuda_bf16.h>
#include <cstdint>

// Problem constants
#define BB 8
#define NN 2048
#define DD 256
#define LL 2
#define MROWS (BB * NN)   // 16384

#define KC 64             // K per pipeline chunk
#define NSTAGES 3

// smem geometry (padded, no swizzle) — shared by both MMA kernels
#define PADK 72                      // 64 + 8 bf16 pad
#define ROWB (PADK * 2)              // 144 bytes per row
#define ASTAGE (128 * ROWB)          // 18432 B
#define STAGE_BYTES (2 * ASTAGE)     // 36864 B (A + B)
#define MMA_SMEM (NSTAGES * STAGE_BYTES)  // 110592 B

// ---------------------------------------------------------------------------
// Scratch (static __device__ arrays — no allocation allowed)
// ---------------------------------------------------------------------------
__device__ __nv_bfloat16 g_adj_bf[(size_t)BB * NN * NN];    // adj bf16
__device__ __nv_bfloat16 g_nodes_bf[(size_t)MROWS * DD];    // nodes bf16 (plain)
__device__ __nv_bfloat16 g_xbf[(size_t)MROWS * DD];         // activations bf16 (plain)
__device__ __nv_bfloat16 g_xT[(size_t)BB * DD * NN];        // x transposed [b][d][n]
__device__ __nv_bfloat16 g_S[(size_t)MROWS * DD];           // S = adj @ x (bf16)
__device__ __nv_bfloat16 g_W0bf[(size_t)LL * DD * DD];      // W0_w bf16
__device__ __nv_bfloat16 g_Wrbf[(size_t)LL * DD * DD];      // Wr_w bf16
__device__ float g_denom[MROWS];                            // row-sum(adj) + 1

// ---------------------------------------------------------------------------
// PTX helpers (plain-sm_103-safe)
// ---------------------------------------------------------------------------
__device__ __forceinline__ uint32_t smem_u32(const void* p) {
    uint32_t a;
    asm("{ .reg .u64 t; cvta.to.shared.u64 t, %1; cvt.u32.u64 %0, t; }" : "=r"(a) : "l"(p));
    return a;
}
__device__ __forceinline__ void cp_async16(uint32_t saddr, const void* g) {
    asm volatile("cp.async.cg.shared.global [%0], [%1], 16;" :: "r"(saddr), "l"(g) : "memory");
}
__device__ __forceinline__ void cp_commit() {
    asm volatile("cp.async.commit_group;" ::: "memory");
}
template <int N>
__device__ __forceinline__ void cp_wait() {
    asm volatile("cp.async.wait_group %0;" :: "n"(N) : "memory");
}
__device__ __forceinline__ void ldsm_x4(uint32_t (&r)[4], uint32_t addr) {
    asm volatile("ldmatrix.sync.aligned.m8n8.x4.shared.b16 {%0,%1,%2,%3}, [%4];"
                 : "=r"(r[0]), "=r"(r[1]), "=r"(r[2]), "=r"(r[3]) : "r"(addr));
}
__device__ __forceinline__ void mma_bf16(float (&c)[4], const uint32_t (&a)[4],
                                         uint32_t b0, uint32_t b1) {
    asm volatile(
        "mma.sync.aligned.m16n8k16.row.col.f32.bf16.bf16.f32 "
        "{%0,%1,%2,%3}, {%4,%5,%6,%7}, {%8,%9}, {%0,%1,%2,%3};"
        : "+f"(c[0]), "+f"(c[1]), "+f"(c[2]), "+f"(c[3])
        : "r"(a[0]), "r"(a[1]), "r"(a[2]), "r"(a[3]), "r"(b0), "r"(b1));
}
__device__ __forceinline__ uint32_t pack_bf16x2(float x, float y) {
    __nv_bfloat162 v = __floats2bfloat162_rn(x, y);
    return *(uint32_t*)&v;
}

// ---------------------------------------------------------------------------
// One conversion kernel: adj->bf16 + denom, nodes->bf16, weights->bf16
// ---------------------------------------------------------------------------
#define NB_NODES ((MROWS * DD) / (256 * 8))           // 2048
#define NB_W ((LL * DD * DD) / (256 * 8))             // 64

__global__ void convert_all_kernel(const float* __restrict__ adj,
                                   const float* __restrict__ nodes,
                                   const float* __restrict__ W0w,
                                   const float* __restrict__ Wrw) {
    int bid = blockIdx.x;
    int tid = threadIdx.x;

    if (bid < MROWS) {
        int row = bid;
        const float4* src = (const float4*)(adj + (size_t)row * NN);
        __nv_bfloat16* dst = g_adj_bf + (size_t)row * NN;
        float4 v0 = src[tid * 2 + 0];
        float4 v1 = src[tid * 2 + 1];
        float s = v0.x + v0.y + v0.z + v0.w + v1.x + v1.y + v1.z + v1.w;
        __nv_bfloat16 tmp[8];
        tmp[0] = __float2bfloat16(v0.x); tmp[1] = __float2bfloat16(v0.y);
        tmp[2] = __float2bfloat16(v0.z); tmp[3] = __float2bfloat16(v0.w);
        tmp[4] = __float2bfloat16(v1.x); tmp[5] = __float2bfloat16(v1.y);
        tmp[6] = __float2bfloat16(v1.z); tmp[7] = __float2bfloat16(v1.w);
        *(uint4*)(dst + tid * 8) = *(const uint4*)tmp;

        __shared__ float red[8];
#pragma unroll
        for (int o = 16; o; o >>= 1) s += __shfl_xor_sync(0xffffffffu, s, o);
        if ((tid & 31) == 0) red[tid >> 5] = s;
        __syncthreads();
        if (tid < 8) {
            float t = red[tid];
#pragma unroll
            for (int o = 4; o; o >>= 1) t += __shfl_xor_sync(0xffu, t, o);
            if (tid == 0) g_denom[row] = t + 1.0f;
        }
        return;
    }

    const float* src;
    __nv_bfloat16* dst;
    size_t off;
    int b2 = bid - MROWS;
    if (b2 < NB_NODES) {
        src = nodes; dst = g_nodes_bf; off = (size_t)b2 * 256 * 8;
    } else if (b2 < NB_NODES + NB_W) {
        src = W0w; dst = g_W0bf; off = (size_t)(b2 - NB_NODES) * 256 * 8;
    } else {
        src = Wrw; dst = g_Wrbf; off = (size_t)(b2 - NB_NODES - NB_W) * 256 * 8;
    }
    size_t p = off + (size_t)tid * 8;
    float4 v0 = *(const float4*)(src + p);
    float4 v1 = *(const float4*)(src + p + 4);
    __nv_bfloat16 tmp[8];
    tmp[0] = __float2bfloat16(v0.x); tmp[1] = __float2bfloat16(v0.y);
    tmp[2] = __float2bfloat16(v0.z); tmp[3] = __float2bfloat16(v0.w);
    tmp[4] = __float2bfloat16(v1.x); tmp[5] = __float2bfloat16(v1.y);
    tmp[6] = __float2bfloat16(v1.z); tmp[7] = __float2bfloat16(v1.w);
    *(uint4*)(dst + p) = *(const uint4*)tmp;
}

// ---------------------------------------------------------------------------
// transpose nodes_bf [b*2048+n][256] -> g_xT [b][d][n]   (layer-0 nn B operand)
//   grid (2 d-tiles, 16 n-tiles, 8 b), block 256, 128x128 smem tile
// ---------------------------------------------------------------------------
__global__ void transpose_nodes_kernel() {
    __shared__ __nv_bfloat16 sm[128 * 144];
    int tid = threadIdx.x;
    int dt = blockIdx.x, nt = blockIdx.y, b = blockIdx.z;

#pragma unroll
    for (int i = 0; i < 8; ++i) {
        int idx = i * 256 + tid;
        int r = idx >> 4, ch = idx & 15;          // r = n-row, ch = 16B chunk of d
        const __nv_bfloat16* src = g_nodes_bf +
            ((size_t)b * NN + nt * 128 + r) * DD + dt * 128 + ch * 8;
        *(uint4*)&sm[r * 144 + ch * 8] = *(const uint4*)src;
    }
    __syncthreads();
#pragma unroll
    for (int i = 0; i < 8; ++i) {
        int idx = i * 256 + tid;
        int d = idx >> 4, ch = idx & 15;          // d = output row, ch = n chunk
        __nv_bfloat16 tmp[8];
#pragma unroll
        for (int j = 0; j < 8; ++j) tmp[j] = sm[(ch * 8 + j) * 144 + d];
        *(uint4*)(g_xT + (size_t)b * DD * NN + (size_t)(dt * 128 + d) * NN
                  + nt * 128 + ch * 8) = *(const uint4*)tmp;
    }
}

// ---------------------------------------------------------------------------
// Big GEMM: S = adj @ x   (B = g_xT, K-major)
//   grid (2, 16, 8) = 256 CTAs, block 256, 2 CTA/SM
// ---------------------------------------------------------------------------
#define NCHUNK (NN / KC)  // 32

__global__ void __launch_bounds__(256, 2)
nn_mma_kernel() {
    extern __shared__ char smem[];
    uint32_t sb = smem_u32(smem);

    int tid = threadIdx.x;
    int lane = tid & 31, wid = tid >> 5;
    int warp_m = wid & 3, warp_n = wid >> 2;
    int b = blockIdx.z;
    int row0 = blockIdx.y * 128;
    int col0 = blockIdx.x * 128;

    const __nv_bfloat16* Ag = g_adj_bf + (size_t)b * NN * NN + (size_t)row0 * NN;
    const __nv_bfloat16* Bg = g_xT + (size_t)b * DD * NN + (size_t)col0 * NN;

    float acc[2][8][4];
#pragma unroll
    for (int i = 0; i < 2; ++i)
#pragma unroll
        for (int j = 0; j < 8; ++j)
#pragma unroll
            for (int q = 0; q < 4; ++q) acc[i][j][q] = 0.f;

    uint32_t a_base = sb + (uint32_t)((warp_m * 32 + (lane & 15)) * ROWB + (lane >> 4) * 16);
    uint32_t b_base = sb + ASTAGE +
                      (uint32_t)((warp_n * 64 + (lane & 15)) * ROWB + (lane >> 4) * 16);

    auto load_stage = [&](int c, int s) {
        uint32_t as = sb + s * STAGE_BYTES;
        uint32_t bs = as + ASTAGE;
        int k0 = c * KC;
#pragma unroll
        for (int i = 0; i < 4; ++i) {
            int idx = i * 256 + tid;
            int r = idx >> 3, ch = idx & 7;
            cp_async16(as + r * ROWB + ch * 16, Ag + (size_t)r * NN + k0 + ch * 8);
        }
#pragma unroll
        for (int i = 0; i < 4; ++i) {
            int idx = i * 256 + tid;
            int r = idx >> 3, ch = idx & 7;
            cp_async16(bs + r * ROWB + ch * 16, Bg + (size_t)r * NN + k0 + ch * 8);
        }
        cp_commit();
    };

    auto compute_stage = [&](int s) {
        uint32_t as = a_base + s * STAGE_BYTES;
        uint32_t bs = b_base + s * STAGE_BYTES;
#pragma unroll
        for (int ks = 0; ks < 4; ++ks) {
            uint32_t af[2][4];
            ldsm_x4(af[0], as + 0 * 16 * ROWB + ks * 32);
            ldsm_x4(af[1], as + 1 * 16 * ROWB + ks * 32);
            uint32_t bf[4][4];
#pragma unroll
            for (int n2 = 0; n2 < 4; ++n2)
                ldsm_x4(bf[n2], bs + n2 * 16 * ROWB + ks * 32);
#pragma unroll
            for (int mf = 0; mf < 2; ++mf)
#pragma unroll
                for (int nf = 0; nf < 8; ++nf)
                    mma_bf16(acc[mf][nf], af[mf], bf[nf >> 1][nf & 1],
                             bf[nf >> 1][(nf & 1) + 2]);
        }
    };

    load_stage(0, 0);
    load_stage(1, 1);

    for (int c = 0; c < NCHUNK; ++c) {
        if (c + 1 < NCHUNK) cp_wait<1>(); else cp_wait<0>();
        __syncthreads();
        if (c + 2 < NCHUNK) load_stage(c + 2, (c + 2) % NSTAGES);
        compute_stage(c % NSTAGES);
    }

    // epilogue: raw bf16 store of S
    int g = lane >> 2, tg = lane & 3;
#pragma unroll
    for (int mf = 0; mf < 2; ++mf) {
#pragma unroll
        for (int half = 0; half < 2; ++half) {
            int row = row0 + warp_m * 32 + mf * 16 + half * 8 + g;
            size_t grow = (size_t)b * NN + row;
#pragma unroll
            for (int nf = 0; nf < 8; ++nf) {
                int col = col0 + warp_n * 64 + nf * 8 + tg * 2;
                *(uint32_t*)(g_S + grow * DD + col) =
                    pack_bf16x2(acc[mf][nf][half * 2 + 0], acc[mf][nf][half * 2 + 1]);
            }
        }
    }
}

// ---------------------------------------------------------------------------
// epi kernel: acc = S@Wr^T + x@W0^T   (two K=256 passes, 8 chunks, 3-stage)
//   out = relu((acc + b0 + (denom-1)*br) / denom)
//   final: dout = nodes + out (fp32); else: g_xbf (plain) + g_xT (transposed)
//   grid (2, 128), block 256, 2 CTA/SM
// ---------------------------------------------------------------------------
__global__ void __launch_bounds__(256, 2)
epi_mma_kernel(int use_x,
               const float* __restrict__ b0,
               const float* __restrict__ br,
               const float* __restrict__ nodes,
               float* __restrict__ dout,
               int layer, int final_layer) {
    extern __shared__ char smem[];
    uint32_t sb = smem_u32(smem);
    __nv_bfloat16* Ts = (__nv_bfloat16*)smem;    // aliases stage mem (epilogue only)

    int tid = threadIdx.x;
    int lane = tid & 31, wid = tid >> 5;
    int warp_m = wid & 3, warp_n = wid >> 2;
    int row0 = blockIdx.y * 128;
    int col0w = blockIdx.x * 128;                // output feature tile

    const __nv_bfloat16* A0 = g_S + (size_t)row0 * DD;
    const __nv_bfloat16* A1 = (use_x ? g_xbf : g_nodes_bf) + (size_t)row0 * DD;
    const __nv_bfloat16* B0 = g_Wrbf + (size_t)layer * DD * DD + (size_t)col0w * DD;
    const __nv_bfloat16* B1 = g_W0bf + (size_t)layer * DD * DD + (size_t)col0w * DD;

    float acc[2][8][4];
#pragma unroll
    for (int i = 0; i < 2; ++i)
#pragma unroll
        for (int j = 0; j < 8; ++j)
#pragma unroll
            for (int q = 0; q < 4; ++q) acc[i][j][q] = 0.f;

    uint32_t a_base = sb + (uint32_t)((warp_m * 32 + (lane & 15)) * ROWB + (lane >> 4) * 16);
    uint32_t b_base = sb + ASTAGE +
                      (uint32_t)((warp_n * 64 + (lane & 15)) * ROWB + (lane >> 4) * 16);

    // chunk c in [0,8): c<4 -> (S, Wr) pass; c>=4 -> (x, W0) pass
    auto load_stage = [&](int c, int s) {
        uint32_t as = sb + s * STAGE_BYTES;
        uint32_t bs = as + ASTAGE;
        const __nv_bfloat16* Ag = (c < 4) ? A0 : A1;
        const __nv_bfloat16* Bg = (c < 4) ? B0 : B1;
        int k0 = (c & 3) * KC;
#pragma unroll
        for (int i = 0; i < 4; ++i) {
            int idx = i * 256 + tid;
            int r = idx >> 3, ch = idx & 7;
            cp_async16(as + r * ROWB + ch * 16, Ag + (size_t)r * DD + k0 + ch * 8);
        }
#pragma unroll
        for (int i = 0; i < 4; ++i) {
            int idx = i * 256 + tid;
            int r = idx >> 3, ch = idx & 7;
            cp_async16(bs + r * ROWB + ch * 16, Bg + (size_t)r * DD + k0 + ch * 8);
        }
        cp_commit();
    };

    auto compute_stage = [&](int s) {
        uint32_t as = a_base + s * STAGE_BYTES;
        uint32_t bs = b_base + s * STAGE_BYTES;
#pragma unroll
        for (int ks = 0; ks < 4; ++ks) {
            uint32_t af[2][4];
            ldsm_x4(af[0], as + 0 * 16 * ROWB + ks * 32);
            ldsm_x4(af[1], as + 1 * 16 * ROWB + ks * 32);
            uint32_t bf[4][4];
#pragma unroll
            for (int n2 = 0; n2 < 4; ++n2)
                ldsm_x4(bf[n2], bs + n2 * 16 * ROWB + ks * 32);
#pragma unroll
            for (int mf = 0; mf < 2; ++mf)
#pragma unroll
                for (int nf = 0; nf < 8; ++nf)
                    mma_bf16(acc[mf][nf], af[mf], bf[nf >> 1][nf & 1],
                             bf[nf >> 1][(nf & 1) + 2]);
        }
    };

    load_stage(0, 0);
    load_stage(1, 1);
    for (int c = 0; c < 8; ++c) {
        if (c + 1 < 8) cp_wait<1>(); else cp_wait<0>();
        __syncthreads();
        if (c + 2 < 8) load_stage(c + 2, (c + 2) % NSTAGES);
        compute_stage(c % NSTAGES);
    }

    int g = lane >> 2, tg = lane & 3;

    if (final_layer) {
#pragma unroll
        for (int mf = 0; mf < 2; ++mf)
#pragma unroll
            for (int half = 0; half < 2; ++half) {
                int rl = warp_m * 32 + mf * 16 + half * 8 + g;
                size_t grow = (size_t)row0 + rl;
                float den = g_denom[grow];
                float inv = 1.0f / den;
                float rs = den - 1.0f;
#pragma unroll
                for (int nf = 0; nf < 8; ++nf) {
                    int m = col0w + warp_n * 64 + nf * 8 + tg * 2;
                    float2 bi0 = *(const float2*)(b0 + m);
                    float2 bir = *(const float2*)(br + m);
                    float vx = fmaxf((acc[mf][nf][half * 2 + 0] + bi0.x + rs * bir.x) * inv, 0.f);
                    float vy = fmaxf((acc[mf][nf][half * 2 + 1] + bi0.y + rs * bir.y) * inv, 0.f);
                    float2 nd = *(const float2*)(nodes + grow * DD + m);
                    *(float2*)(dout + grow * DD + m) = make_float2(vx + nd.x, vy + nd.y);
                }
            }
    } else {
        __syncthreads();     // stage smem fully consumed; safe to alias as Ts
#pragma unroll
        for (int mf = 0; mf < 2; ++mf)
#pragma unroll
            for (int half = 0; half < 2; ++half) {
                int rl = warp_m * 32 + mf * 16 + half * 8 + g;
                size_t grow = (size_t)row0 + rl;
                float den = g_denom[grow];
                float inv = 1.0f / den;
                float rs = den - 1.0f;
#pragma unroll
                for (int nf = 0; nf < 8; ++nf) {
                    int cl = warp_n * 64 + nf * 8 + tg * 2;
                    int m = col0w + cl;
                    float2 bi0 = *(const float2*)(b0 + m);
                    float2 bir = *(const float2*)(br + m);
                    float vx = fmaxf((acc[mf][nf][half * 2 + 0] + bi0.x + rs * bir.x) * inv, 0.f);
                    float vy = fmaxf((acc[mf][nf][half * 2 + 1] + bi0.y + rs * bir.y) * inv, 0.f);
                    // plain write (next epi's A operand)
                    *(uint32_t*)(g_xbf + grow * DD + m) = pack_bf16x2(vx, vy);
                    // transposed staging (next nn's B operand)
                    Ts[(size_t)cl * 136 + rl] = __float2bfloat16(vx);
                    Ts[(size_t)(cl + 1) * 136 + rl] = __float2bfloat16(vy);
                }
            }
        __syncthreads();
        int b = row0 >> 11;
        int nloc = row0 & 2047;
        int dl = tid >> 1, seg = tid & 1;
        __nv_bfloat16* dst = g_xT + (size_t)b * DD * NN + (size_t)(col0w + dl) * NN
                             + nloc + seg * 64;
        const __nv_bfloat16* srcp = Ts + (size_t)dl * 136 + seg * 64;
#pragma unroll
        for (int q = 0; q < 8; ++q)
            *(uint4*)(dst + q * 8) = *(const uint4*)(srcp + q * 8);
    }
}

// ---------------------------------------------------------------------------
// Launch
// ---------------------------------------------------------------------------
extern "C" void kernel_launch(void* const* d_in, const int* in_sizes, int n_in,
                              void* d_out, int out_size) {
    const float* nodes = (const float*)d_in[0];
    const float* adj   = (const float*)d_in[1];
    const float* W0w   = (const float*)d_in[2];
    const float* W0b   = (const float*)d_in[3];
    const float* Wrw   = (const float*)d_in[4];
    const float* Wrb   = (const float*)d_in[5];
    float* out = (float*)d_out;

    cudaFuncSetAttribute(nn_mma_kernel, cudaFuncAttributeMaxDynamicSharedMemorySize,
                         MMA_SMEM);
    cudaFuncSetAttribute(epi_mma_kernel, cudaFuncAttributeMaxDynamicSharedMemorySize,
                         MMA_SMEM);

    convert_all_kernel<<<MROWS + NB_NODES + 2 * NB_W, 256>>>(adj, nodes, W0w, Wrw);

    dim3 grid_tr(2, 16, 8);                // nodes -> g_xT
    transpose_nodes_kernel<<<grid_tr, 256>>>();

    dim3 grid_nn(DD / 128, NN / 128, BB);  // (2, 16, 8)
    dim3 grid_epi(2, MROWS / 128);         // (2, 128)

    for (int l = 0; l < LL; ++l) {
        nn_mma_kernel<<<grid_nn, 256, MMA_SMEM>>>();   // S = adj @ x_l
        epi_mma_kernel<<<grid_epi, 256, MMA_SMEM>>>(
            (l == 0) ? 0 : 1,
            W0b + (size_t)l * DD, Wrb + (size_t)l * DD,
            nodes, out, l, (l == LL - 1) ? 1 : 0);
    }
}